// round 10
// baseline (speedup 1.0000x reference)
#include <cuda_runtime.h>

#define BNN 16384   // 16*32*32

// ---------------- scratch (device globals) ----------------------------------
__device__ float g_Koa[512*128];
__device__ float g_Qoa[512*128];
__device__ float g_Voa[512*128];
__device__ float g_Vop[512*128];
__device__ float g_Ko [512*128];
__device__ float g_Qo [512*128];
__device__ float g_AVO[512*128];
__device__ float g_A  [512*64];
__device__ float g_C  [512*64];
__device__ float g_woa[512*32];
__device__ float g_M  [16384*128];   // per-(b,k,j) noise i-sum, 8MB
__device__ float g_WT [128*64];      // W1b^T [d][h]
__device__ unsigned int g_ctr;       // atomic tile queue

__device__ __forceinline__ float dot4(float4 a, float4 b){
    return a.x*b.x + a.y*b.y + a.z*b.z + a.w*b.w;
}

// ---------------- proj (obs-action branch, E=144 compile-time) ---------------
__global__ __launch_bounds__(256) void proj_oa_kernel(
    const float* __restrict__ states, const float* __restrict__ policies,
    const float* __restrict__ actions,
    const float* __restrict__ Wk_oa, const float* __restrict__ Wq_oa,
    const float* __restrict__ Wv_oa)
{
    constexpr int E = 144;
    __shared__ float IN [32*148];
    __shared__ float Wsm[32*148];
    int b = blockIdx.x, m = blockIdx.y, dz = blockIdx.z;
    int tid = threadIdx.x;
    const float* W = (m==0)?Wk_oa:(m==1)?Wq_oa:Wv_oa;
    float* OUT = (m==0)?g_Koa:(m==1)?g_Qoa:(m==2)?g_Voa:g_Vop;
    const float* extra = (m==3) ? policies : actions;

    #pragma unroll
    for (int it = 0; it < 18; it++) {
        int idx = tid + it*256;
        int a = idx / E, e = idx - a*E;
        float v = (e < 128) ? states[(b*32+a)*128 + e]
                            : extra[(b*32+a)*16 + (e-128)];
        IN[a*148 + e] = v;
    }
    #pragma unroll
    for (int it = 0; it < 18; it++) {
        int idx = tid + it*256;
        int r = idx / E, e = idx - r*E;
        Wsm[r*148 + e] = W[(dz*32+r)*E + e];
    }
    __syncthreads();

    int r = tid & 31, g = tid >> 5;
    float acc0=0.f, acc1=0.f, acc2=0.f, acc3=0.f;
    const float4* wr = (const float4*)(Wsm + r*148);
    const float4* x0 = (const float4*)(IN + (g*4+0)*148);
    const float4* x1 = (const float4*)(IN + (g*4+1)*148);
    const float4* x2 = (const float4*)(IN + (g*4+2)*148);
    const float4* x3 = (const float4*)(IN + (g*4+3)*148);
    #pragma unroll
    for (int e4 = 0; e4 < E/4; e4++) {
        float4 w = wr[e4];
        acc0 += dot4(w, x0[e4]);
        acc1 += dot4(w, x1[e4]);
        acc2 += dot4(w, x2[e4]);
        acc3 += dot4(w, x3[e4]);
    }
    int dg = dz*32 + r;
    OUT[(b*32 + g*4+0)*128 + dg] = acc0;
    OUT[(b*32 + g*4+1)*128 + dg] = acc1;
    OUT[(b*32 + g*4+2)*128 + dg] = acc2;
    OUT[(b*32 + g*4+3)*128 + dg] = acc3;
}

// ---------------- proj (obs-only branch, E=128 compile-time) -----------------
__global__ __launch_bounds__(256) void proj_o_kernel(
    const float* __restrict__ states,
    const float* __restrict__ Wk_o, const float* __restrict__ Wq_o,
    const float* __restrict__ Wv_o)
{
    __shared__ float IN [32*132];
    __shared__ float Wsm[32*132];
    int b = blockIdx.x, m = blockIdx.y, dz = blockIdx.z;
    int tid = threadIdx.x;
    const float* W = (m==0)?Wk_o:(m==1)?Wq_o:Wv_o;
    float* OUT = (m==0)?g_Ko:(m==1)?g_Qo:g_AVO;

    const float4* S4 = (const float4*)(states + b*32*128);
    const float4* W4 = (const float4*)(W + dz*32*128);
    #pragma unroll
    for (int it = 0; it < 4; it++) {
        int idx = tid + it*256;               // float4 index
        int a = idx >> 5, e4 = idx & 31;
        *(float4*)(IN  + a*132 + e4*4) = S4[idx];
        *(float4*)(Wsm + a*132 + e4*4) = W4[idx];
    }
    __syncthreads();

    int r = tid & 31, g = tid >> 5;
    float acc0=0.f, acc1=0.f, acc2=0.f, acc3=0.f;
    const float4* wr = (const float4*)(Wsm + r*132);
    const float4* x0 = (const float4*)(IN + (g*4+0)*132);
    const float4* x1 = (const float4*)(IN + (g*4+1)*132);
    const float4* x2 = (const float4*)(IN + (g*4+2)*132);
    const float4* x3 = (const float4*)(IN + (g*4+3)*132);
    #pragma unroll
    for (int e4 = 0; e4 < 32; e4++) {
        float4 w = wr[e4];
        acc0 += dot4(w, x0[e4]);
        acc1 += dot4(w, x1[e4]);
        acc2 += dot4(w, x2[e4]);
        acc3 += dot4(w, x3[e4]);
    }
    int dg = dz*32 + r;
    OUT[(b*32 + g*4+0)*128 + dg] = acc0;
    OUT[(b*32 + g*4+1)*128 + dg] = acc1;
    OUT[(b*32 + g*4+2)*128 + dg] = acc2;
    OUT[(b*32 + g*4+3)*128 + dg] = acc3;
}

// ---------------- W1b transpose (once, tiny) ---------------------------------
__global__ void wtrans_kernel(const float* __restrict__ W1)
{
    int idx = blockIdx.x*256 + threadIdx.x;   // 8192
    int h = idx >> 7, d = idx & 127;
    g_WT[d*64 + h] = W1[h*256 + 128 + d];
}

// ---------------- kernel 2: fused attention (both branches) + A/C fold -------
__global__ __launch_bounds__(256) void attac_kernel(
    const float* __restrict__ W1, float* __restrict__ out)
{
    __shared__ float sbig[8320];   // att: sQ+sV; ac: W^T (128*65)
    __shared__ float sK[8*128];    // att K rows; later wfo rows
    __shared__ float sS[8*128];    // raw S
    __shared__ float sD[8*128];    // (Vop-Voa)/32
    float* sQ  = sbig;
    float* sV  = sbig + 4224;
    float* sWT = sbig;

    int b = blockIdx.x, q = blockIdx.y, tid = threadIdx.x;
    int kk = tid >> 5, i = tid & 31, k = q*8 + kk;

    for (int p = 0; p < 2; p++) {
        const float* Qp = p ? g_Qo  : g_Qoa;
        const float* Kp = p ? g_Ko  : g_Koa;
        const float* Vp = p ? g_AVO : g_Voa;
        if (p) __syncthreads();
        const float4* Q4 = (const float4*)(Qp + b*32*128);
        const float4* V4 = (const float4*)(Vp + b*32*128);
        for (int idx = tid; idx < 1024; idx += 256) {
            int a = idx >> 5, e4 = idx & 31;
            *(float4*)(sQ + a*132 + e4*4) = Q4[idx];
            ((float4*)sV)[idx] = V4[idx];
        }
        const float4* K4 = (const float4*)(Kp + (b*32 + q*8)*128);
        if (tid < 256) ((float4*)sK)[tid] = K4[tid];
        __syncthreads();

        const float4* qr = (const float4*)(sQ + i*132);
        const float4* kr = (const float4*)(sK + kk*128);
        float acc = 0.f;
        #pragma unroll
        for (int e4 = 0; e4 < 32; e4++) acc += dot4(qr[e4], kr[e4]);
        float v = acc * 0.08838834764831845f;   // 1/sqrt(128)
        float mx = v;
        #pragma unroll
        for (int off = 16; off; off >>= 1) mx = fmaxf(mx, __shfl_xor_sync(0xffffffffu, mx, off));
        float ex = __expf(v - mx);
        float sm = ex;
        #pragma unroll
        for (int off = 16; off; off >>= 1) sm += __shfl_xor_sync(0xffffffffu, sm, off);
        float w = ex / sm;
        out[(p ? 2*BNN : BNN) + (b*32+k)*32 + i] = w;
        if (!p) g_woa[(b*32+k)*32 + i] = w;
        if (p) __syncthreads();

        float4 a4 = make_float4(0.f,0.f,0.f,0.f);
        #pragma unroll
        for (int i2 = 0; i2 < 32; i2++) {
            float wv = __shfl_sync(0xffffffffu, w, i2);
            float4 vv = ((const float4*)sV)[i2*32 + i];
            a4.x += wv*vv.x; a4.y += wv*vv.y; a4.z += wv*vv.z; a4.w += wv*vv.w;
        }
        if (!p) {
            ((float4*)sS)[kk*32 + i] = a4;
        } else {
            float4 sc = make_float4(a4.x*0.03125f, a4.y*0.03125f, a4.z*0.03125f, a4.w*0.03125f);
            ((float4*)sK)[kk*32 + i] = sc;    // wfo
        }
    }
    __syncthreads();

    {
        int base = (b*32 + q*8)*128;
        for (int idx = tid; idx < 1024; idx += 256)
            sD[idx] = (g_Vop[base+idx] - g_Voa[base+idx]) * 0.03125f;
        for (int idx = tid; idx < 8192; idx += 256) {   // W1a^T
            int hh = idx >> 7, e = idx & 127;
            sWT[e*65 + hh] = W1[hh*256 + e];
        }
    }
    __syncthreads();

    int h = tid & 63, grp = tid >> 6;
    const float* wf0 = sK + (grp*2  )*128;
    const float* wf1 = sK + (grp*2+1)*128;
    float accA0 = 0.f, accA1 = 0.f;
    #pragma unroll 4
    for (int e = 0; e < 128; e++) {
        float w = sWT[e*65 + h];
        accA0 += w*wf0[e]; accA1 += w*wf1[e];
    }
    __syncthreads();
    for (int idx = tid; idx < 8192; idx += 256) {       // W1b^T
        int hh = idx >> 7, e = idx & 127;
        sWT[e*65 + hh] = W1[hh*256 + 128 + e];
    }
    __syncthreads();

    const float* s0 = sS + grp*2*128; const float* s1 = s0 + 128;
    const float* d0 = sD + grp*2*128; const float* d1 = d0 + 128;
    float aS0=0.f, aS1=0.f, aD0=0.f, aD1=0.f, aW=0.f;
    #pragma unroll 4
    for (int e = 0; e < 128; e++) {
        float w = sWT[e*65 + h];
        aW  += w;
        aS0 += w*s0[e]; aS1 += w*s1[e];
        aD0 += w*d0[e]; aD1 += w*d1[e];
    }
    int ga = b*32 + q*8 + grp*2;
    g_A[ ga   *64 + h] = accA0 + 0.03125f*aS0 - 0.05f*aW;
    g_A[(ga+1)*64 + h] = accA1 + 0.03125f*aS1 - 0.05f*aW;
    g_C[ ga   *64 + h] = aD0;
    g_C[(ga+1)*64 + h] = aD1;
}

// ---------------- kernel 3: pure noise streaming (atomic work queue) ---------
// grid 148 x 1024: one block per SM, 32 warps/SM, warps grab 16KB tiles.
__global__ __launch_bounds__(1024) void reduce_kernel(const float4* __restrict__ np)
{
    int lane = threadIdx.x & 31;
    for (;;) {
        unsigned int tile;
        if (lane == 0) tile = atomicAdd(&g_ctr, 1u);
        tile = __shfl_sync(0xffffffffu, tile, 0);
        if (tile >= 16384u) break;
        const float4* p = np + ((long)tile << 10) + lane;
        float4 acc = make_float4(0.f,0.f,0.f,0.f);
        #pragma unroll
        for (int bb = 0; bb < 4; bb++) {
            float4 v[8];
            #pragma unroll
            for (int u = 0; u < 8; u++) v[u] = __ldcs(p + ((bb*8 + u) << 5));
            #pragma unroll
            for (int u = 0; u < 8; u++) {
                acc.x += v[u].x; acc.y += v[u].y; acc.z += v[u].z; acc.w += v[u].w;
            }
        }
        ((float4*)g_M)[(tile << 5) + lane] = acc;
    }
}

// ---------------- kernel 4: GEMV + epilogue -> value -------------------------
// grid 128 x 512: warp handles 8 rows (one bk) as 2 register-tiled groups of 4.
__global__ __launch_bounds__(512) void gemv_kernel(
    const float* __restrict__ W2, float* __restrict__ out)
{
    __shared__ float Ms[16*512];     // per-warp 4 staged rows (32KB)
    int tid = threadIdx.x;
    int w = tid >> 5, lane = tid & 31;
    int wg = blockIdx.x*16 + w;      // 0..2047
    int row0 = wg * 8;               // 8 consecutive rows, same bk
    int bk = row0 >> 5, b = row0 >> 10;

    float2 A2  = *(const float2*)(g_A + bk*64 + 2*lane);
    float w2x = __ldg(W2 + 2*lane), w2y = __ldg(W2 + 2*lane + 1);
    float* ms = Ms + w*512;
    const float* wt = g_WT + 2*lane;

    #pragma unroll
    for (int pp = 0; pp < 2; pp++) {
        int r0 = row0 + pp*4;
        #pragma unroll
        for (int qq = 0; qq < 4; qq++)
            *(float4*)(ms + qq*128 + lane*4) = ((const float4*)g_M)[(r0+qq)*32 + lane];
        __syncwarp();

        float a0x=0.f,a0y=0.f,a1x=0.f,a1y=0.f,a2x=0.f,a2y=0.f,a3x=0.f,a3y=0.f;
        #pragma unroll 4
        for (int d = 0; d < 128; d++) {
            float2 wv = *(const float2*)(wt + d*64);   // L1-hot, coalesced
            float m0 = ms[d], m1 = ms[128+d], m2 = ms[256+d], m3 = ms[384+d];
            a0x += m0*wv.x; a0y += m0*wv.y;
            a1x += m1*wv.x; a1y += m1*wv.y;
            a2x += m2*wv.x; a2y += m2*wv.y;
            a3x += m3*wv.x; a3y += m3*wv.y;
        }
        #pragma unroll
        for (int qq = 0; qq < 4; qq++) {
            int row = r0 + qq, j = row & 31;
            float hx = (qq==0)?a0x:(qq==1)?a1x:(qq==2)?a2x:a3x;
            float hy = (qq==0)?a0y:(qq==1)?a1y:(qq==2)?a2y:a3y;
            float wo = g_woa[row];
            float2 c2 = *(const float2*)(g_C + (b*32 + j)*64 + 2*lane);
            float q0 = A2.x + wo*c2.x + 0.003125f*hx;
            float q1 = A2.y + wo*c2.y + 0.003125f*hy;
            q0 = q0 > 0.f ? q0 : 0.01f*q0;
            q1 = q1 > 0.f ? q1 : 0.01f*q1;
            float val = q0*w2x + q1*w2y;
            #pragma unroll
            for (int off = 16; off; off >>= 1) val += __shfl_down_sync(0xffffffffu, val, off);
            if (lane == 0) out[row] = val;
        }
        __syncwarp();
    }
}

// ---------------- launch: fork streaming at t=0 -------------------------------
extern "C" void kernel_launch(void* const* d_in, const int* in_sizes, int n_in,
                              void* d_out, int out_size)
{
    const float* states   = (const float*)d_in[0];
    const float* policies = (const float*)d_in[1];
    const float* actions  = (const float*)d_in[2];
    const float* noise    = (const float*)d_in[3];
    const float* Wk_oa    = (const float*)d_in[4];
    const float* Wq_oa    = (const float*)d_in[5];
    const float* Wv_oa    = (const float*)d_in[6];
    const float* Wk_o     = (const float*)d_in[7];
    const float* Wq_o     = (const float*)d_in[8];
    const float* Wv_o     = (const float*)d_in[9];
    const float* W1       = (const float*)d_in[10];
    const float* W2       = (const float*)d_in[11];
    float* out = (float*)d_out;

    static cudaStream_t s2 = nullptr;
    static cudaEvent_t evA = nullptr, evB = nullptr;
    static void* ctr = nullptr;
    if (!s2) {
        cudaStreamCreateWithFlags(&s2, cudaStreamNonBlocking);
        cudaEventCreateWithFlags(&evA, cudaEventDisableTiming);
        cudaEventCreateWithFlags(&evB, cudaEventDisableTiming);
        cudaGetSymbolAddress(&ctr, g_ctr);
    }

    // fork: noise reduction (depends only on noise) runs concurrently
    cudaEventRecord(evA, 0);
    cudaStreamWaitEvent(s2, evA, 0);
    cudaMemsetAsync(ctr, 0, 4, s2);
    reduce_kernel<<<148, 1024, 0, s2>>>((const float4*)noise);
    cudaEventRecord(evB, s2);

    proj_oa_kernel<<<dim3(16,4,4), 256>>>(states, policies, actions,
                                          Wk_oa, Wq_oa, Wv_oa);
    proj_o_kernel<<<dim3(16,3,4), 256>>>(states, Wk_o, Wq_o, Wv_o);
    wtrans_kernel<<<32, 256>>>(W1);
    attac_kernel<<<dim3(16,4), 256>>>(W1, out);

    cudaStreamWaitEvent(0, evB, 0);
    gemv_kernel<<<128, 512>>>(W2, out);
}

// round 13
// speedup vs baseline: 1.5260x; 1.5260x over previous
#include <cuda_runtime.h>

#define BNN 16384   // 16*32*32

// ---------------- scratch (device globals) ----------------------------------
__device__ float g_Koa[512*128];
__device__ float g_Qoa[512*128];
__device__ float g_Voa[512*128];
__device__ float g_Vop[512*128];
__device__ float g_Ko [512*128];
__device__ float g_Qo [512*128];
__device__ float g_AVO[512*128];
__device__ float g_A  [512*64];
__device__ float g_C  [512*64];
__device__ float g_woa[512*32];
__device__ float g_Mh [32768*128];   // per half-tile partial i-sums (16MB)
__device__ float g_WT [128*64];      // W1b^T [d][h]

__device__ __forceinline__ float dot4(float4 a, float4 b){
    return a.x*b.x + a.y*b.y + a.z*b.z + a.w*b.w;
}

// ---------------- proj (obs-action branch, E=144 compile-time) ---------------
__global__ __launch_bounds__(256) void proj_oa_kernel(
    const float* __restrict__ states, const float* __restrict__ policies,
    const float* __restrict__ actions,
    const float* __restrict__ Wk_oa, const float* __restrict__ Wq_oa,
    const float* __restrict__ Wv_oa)
{
    constexpr int E = 144;
    __shared__ float IN [32*148];
    __shared__ float Wsm[32*148];
    int b = blockIdx.x, m = blockIdx.y, dz = blockIdx.z;
    int tid = threadIdx.x;
    const float* W = (m==0)?Wk_oa:(m==1)?Wq_oa:Wv_oa;
    float* OUT = (m==0)?g_Koa:(m==1)?g_Qoa:(m==2)?g_Voa:g_Vop;
    const float* extra = (m==3) ? policies : actions;

    #pragma unroll
    for (int it = 0; it < 18; it++) {
        int idx = tid + it*256;
        int a = idx / E, e = idx - a*E;
        float v = (e < 128) ? states[(b*32+a)*128 + e]
                            : extra[(b*32+a)*16 + (e-128)];
        IN[a*148 + e] = v;
    }
    #pragma unroll
    for (int it = 0; it < 18; it++) {
        int idx = tid + it*256;
        int r = idx / E, e = idx - r*E;
        Wsm[r*148 + e] = W[(dz*32+r)*E + e];
    }
    __syncthreads();

    int r = tid & 31, g = tid >> 5;
    float acc0=0.f, acc1=0.f, acc2=0.f, acc3=0.f;
    const float4* wr = (const float4*)(Wsm + r*148);
    const float4* x0 = (const float4*)(IN + (g*4+0)*148);
    const float4* x1 = (const float4*)(IN + (g*4+1)*148);
    const float4* x2 = (const float4*)(IN + (g*4+2)*148);
    const float4* x3 = (const float4*)(IN + (g*4+3)*148);
    #pragma unroll
    for (int e4 = 0; e4 < E/4; e4++) {
        float4 w = wr[e4];
        acc0 += dot4(w, x0[e4]);
        acc1 += dot4(w, x1[e4]);
        acc2 += dot4(w, x2[e4]);
        acc3 += dot4(w, x3[e4]);
    }
    int dg = dz*32 + r;
    OUT[(b*32 + g*4+0)*128 + dg] = acc0;
    OUT[(b*32 + g*4+1)*128 + dg] = acc1;
    OUT[(b*32 + g*4+2)*128 + dg] = acc2;
    OUT[(b*32 + g*4+3)*128 + dg] = acc3;
}

// ---------------- proj (obs-only branch, E=128 compile-time) -----------------
__global__ __launch_bounds__(256) void proj_o_kernel(
    const float* __restrict__ states,
    const float* __restrict__ Wk_o, const float* __restrict__ Wq_o,
    const float* __restrict__ Wv_o)
{
    __shared__ float IN [32*132];
    __shared__ float Wsm[32*132];
    int b = blockIdx.x, m = blockIdx.y, dz = blockIdx.z;
    int tid = threadIdx.x;
    const float* W = (m==0)?Wk_o:(m==1)?Wq_o:Wv_o;
    float* OUT = (m==0)?g_Ko:(m==1)?g_Qo:g_AVO;

    const float4* S4 = (const float4*)(states + b*32*128);
    const float4* W4 = (const float4*)(W + dz*32*128);
    #pragma unroll
    for (int it = 0; it < 4; it++) {
        int idx = tid + it*256;               // float4 index
        int a = idx >> 5, e4 = idx & 31;
        *(float4*)(IN  + a*132 + e4*4) = S4[idx];
        *(float4*)(Wsm + a*132 + e4*4) = W4[idx];
    }
    __syncthreads();

    int r = tid & 31, g = tid >> 5;
    float acc0=0.f, acc1=0.f, acc2=0.f, acc3=0.f;
    const float4* wr = (const float4*)(Wsm + r*132);
    const float4* x0 = (const float4*)(IN + (g*4+0)*132);
    const float4* x1 = (const float4*)(IN + (g*4+1)*132);
    const float4* x2 = (const float4*)(IN + (g*4+2)*132);
    const float4* x3 = (const float4*)(IN + (g*4+3)*132);
    #pragma unroll
    for (int e4 = 0; e4 < 32; e4++) {
        float4 w = wr[e4];
        acc0 += dot4(w, x0[e4]);
        acc1 += dot4(w, x1[e4]);
        acc2 += dot4(w, x2[e4]);
        acc3 += dot4(w, x3[e4]);
    }
    int dg = dz*32 + r;
    OUT[(b*32 + g*4+0)*128 + dg] = acc0;
    OUT[(b*32 + g*4+1)*128 + dg] = acc1;
    OUT[(b*32 + g*4+2)*128 + dg] = acc2;
    OUT[(b*32 + g*4+3)*128 + dg] = acc3;
}

// ---------------- W1b transpose (once, tiny) ---------------------------------
__global__ void wtrans_kernel(const float* __restrict__ W1)
{
    int idx = blockIdx.x*256 + threadIdx.x;   // 8192
    int h = idx >> 7, d = idx & 127;
    g_WT[d*64 + h] = W1[h*256 + 128 + d];
}

// ---------------- kernel 2: fused attention (both branches) + A/C fold -------
__global__ __launch_bounds__(256) void attac_kernel(
    const float* __restrict__ W1, float* __restrict__ out)
{
    __shared__ float sbig[8320];   // att: sQ+sV; ac: W^T (128*65)
    __shared__ float sK[8*128];    // att K rows; later wfo rows
    __shared__ float sS[8*128];    // raw S
    __shared__ float sD[8*128];    // (Vop-Voa)/32
    float* sQ  = sbig;
    float* sV  = sbig + 4224;
    float* sWT = sbig;

    int b = blockIdx.x, q = blockIdx.y, tid = threadIdx.x;
    int kk = tid >> 5, i = tid & 31, k = q*8 + kk;

    for (int p = 0; p < 2; p++) {
        const float* Qp = p ? g_Qo  : g_Qoa;
        const float* Kp = p ? g_Ko  : g_Koa;
        const float* Vp = p ? g_AVO : g_Voa;
        if (p) __syncthreads();
        const float4* Q4 = (const float4*)(Qp + b*32*128);
        const float4* V4 = (const float4*)(Vp + b*32*128);
        for (int idx = tid; idx < 1024; idx += 256) {
            int a = idx >> 5, e4 = idx & 31;
            *(float4*)(sQ + a*132 + e4*4) = Q4[idx];
            ((float4*)sV)[idx] = V4[idx];
        }
        const float4* K4 = (const float4*)(Kp + (b*32 + q*8)*128);
        if (tid < 256) ((float4*)sK)[tid] = K4[tid];
        __syncthreads();

        const float4* qr = (const float4*)(sQ + i*132);
        const float4* kr = (const float4*)(sK + kk*128);
        float acc = 0.f;
        #pragma unroll
        for (int e4 = 0; e4 < 32; e4++) acc += dot4(qr[e4], kr[e4]);
        float v = acc * 0.08838834764831845f;   // 1/sqrt(128)
        float mx = v;
        #pragma unroll
        for (int off = 16; off; off >>= 1) mx = fmaxf(mx, __shfl_xor_sync(0xffffffffu, mx, off));
        float ex = __expf(v - mx);
        float sm = ex;
        #pragma unroll
        for (int off = 16; off; off >>= 1) sm += __shfl_xor_sync(0xffffffffu, sm, off);
        float w = ex / sm;
        out[(p ? 2*BNN : BNN) + (b*32+k)*32 + i] = w;
        if (!p) g_woa[(b*32+k)*32 + i] = w;
        if (p) __syncthreads();

        float4 a4 = make_float4(0.f,0.f,0.f,0.f);
        #pragma unroll
        for (int i2 = 0; i2 < 32; i2++) {
            float wv = __shfl_sync(0xffffffffu, w, i2);
            float4 vv = ((const float4*)sV)[i2*32 + i];
            a4.x += wv*vv.x; a4.y += wv*vv.y; a4.z += wv*vv.z; a4.w += wv*vv.w;
        }
        if (!p) {
            ((float4*)sS)[kk*32 + i] = a4;
        } else {
            float4 sc = make_float4(a4.x*0.03125f, a4.y*0.03125f, a4.z*0.03125f, a4.w*0.03125f);
            ((float4*)sK)[kk*32 + i] = sc;    // wfo
        }
    }
    __syncthreads();

    {
        int base = (b*32 + q*8)*128;
        for (int idx = tid; idx < 1024; idx += 256)
            sD[idx] = (g_Vop[base+idx] - g_Voa[base+idx]) * 0.03125f;
        for (int idx = tid; idx < 8192; idx += 256) {   // W1a^T
            int hh = idx >> 7, e = idx & 127;
            sWT[e*65 + hh] = W1[hh*256 + e];
        }
    }
    __syncthreads();

    int h = tid & 63, grp = tid >> 6;
    const float* wf0 = sK + (grp*2  )*128;
    const float* wf1 = sK + (grp*2+1)*128;
    float accA0 = 0.f, accA1 = 0.f;
    #pragma unroll 4
    for (int e = 0; e < 128; e++) {
        float w = sWT[e*65 + h];
        accA0 += w*wf0[e]; accA1 += w*wf1[e];
    }
    __syncthreads();
    for (int idx = tid; idx < 8192; idx += 256) {       // W1b^T
        int hh = idx >> 7, e = idx & 127;
        sWT[e*65 + hh] = W1[hh*256 + 128 + e];
    }
    __syncthreads();

    const float* s0 = sS + grp*2*128; const float* s1 = s0 + 128;
    const float* d0 = sD + grp*2*128; const float* d1 = d0 + 128;
    float aS0=0.f, aS1=0.f, aD0=0.f, aD1=0.f, aW=0.f;
    #pragma unroll 4
    for (int e = 0; e < 128; e++) {
        float w = sWT[e*65 + h];
        aW  += w;
        aS0 += w*s0[e]; aS1 += w*s1[e];
        aD0 += w*d0[e]; aD1 += w*d1[e];
    }
    int ga = b*32 + q*8 + grp*2;
    g_A[ ga   *64 + h] = accA0 + 0.03125f*aS0 - 0.05f*aW;
    g_A[(ga+1)*64 + h] = accA1 + 0.03125f*aS1 - 0.05f*aW;
    g_C[ ga   *64 + h] = aD0;
    g_C[(ga+1)*64 + h] = aD1;
}

// ---------------- kernel 3: pure noise streaming, static half-tile stride ----
// grid 296 x 512 = 4736 warps (2 CTAs/SM, single wave). Quantum = half-tile
// (16 i-rows, 8KB). 32768 quanta -> warps do 6 or 7 (1.2% imbalance). No atomics.
__global__ __launch_bounds__(512) void reduce_kernel(const float4* __restrict__ np)
{
    int wg   = blockIdx.x*16 + (threadIdx.x >> 5);   // 0..4735
    int lane = threadIdx.x & 31;
    int nq   = (wg < 4352) ? 7 : 6;                  // 4352*7 + 384*6 = 32768
    for (int q = 0; q < nq; q++) {
        int ht = wg + q*4736;                        // half-tile id
        const float4* p = np + ((long)ht << 9) + lane;
        float4 acc = make_float4(0.f,0.f,0.f,0.f);
        #pragma unroll
        for (int bb = 0; bb < 2; bb++) {
            float4 v[8];
            #pragma unroll
            for (int u = 0; u < 8; u++) v[u] = __ldcs(p + ((bb*8 + u) << 5));
            #pragma unroll
            for (int u = 0; u < 8; u++) {
                acc.x += v[u].x; acc.y += v[u].y; acc.z += v[u].z; acc.w += v[u].w;
            }
        }
        ((float4*)g_Mh)[(ht << 5) + lane] = acc;
    }
}

// ---------------- kernel 4: GEMV + epilogue -> value -------------------------
// grid 512 x 256: block = one (b,k); warp handles 4 rows (j's).
__global__ __launch_bounds__(256) void gemv_kernel(
    const float* __restrict__ W2, float* __restrict__ out)
{
    __shared__ float Ms[8*512];      // per-warp 4 staged rows (16KB)
    int tid = threadIdx.x;
    int w = tid >> 5, lane = tid & 31;
    int bk = blockIdx.x, b = bk >> 5;
    int row0 = bk*32 + w*4;

    float2 A2 = *(const float2*)(g_A + bk*64 + 2*lane);
    float w2x = __ldg(W2 + 2*lane), w2y = __ldg(W2 + 2*lane + 1);
    float* ms = Ms + w*512;
    const float4* Mh4 = (const float4*)g_Mh;

    // stage: sum the two half-tile partials of each row
    #pragma unroll
    for (int qq = 0; qq < 4; qq++) {
        int r = row0 + qq;
        float4 x = Mh4[(r*2    )*32 + lane];
        float4 y = Mh4[(r*2 + 1)*32 + lane];
        x.x += y.x; x.y += y.y; x.z += y.z; x.w += y.w;
        *(float4*)(ms + qq*128 + lane*4) = x;
    }
    __syncwarp();

    const float* wt = g_WT + 2*lane;
    float a0x=0.f,a0y=0.f,a1x=0.f,a1y=0.f,a2x=0.f,a2y=0.f,a3x=0.f,a3y=0.f;
    #pragma unroll 4
    for (int d = 0; d < 128; d++) {
        float2 wv = *(const float2*)(wt + d*64);   // coalesced, L1-hot
        float m0 = ms[d], m1 = ms[128+d], m2 = ms[256+d], m3 = ms[384+d];
        a0x += m0*wv.x; a0y += m0*wv.y;
        a1x += m1*wv.x; a1y += m1*wv.y;
        a2x += m2*wv.x; a2y += m2*wv.y;
        a3x += m3*wv.x; a3y += m3*wv.y;
    }
    #pragma unroll
    for (int qq = 0; qq < 4; qq++) {
        int row = row0 + qq, j = row & 31;
        float hx = (qq==0)?a0x:(qq==1)?a1x:(qq==2)?a2x:a3x;
        float hy = (qq==0)?a0y:(qq==1)?a1y:(qq==2)?a2y:a3y;
        float wo = g_woa[row];
        float2 c2 = *(const float2*)(g_C + (b*32 + j)*64 + 2*lane);
        float q0 = A2.x + wo*c2.x + 0.003125f*hx;
        float q1 = A2.y + wo*c2.y + 0.003125f*hy;
        q0 = q0 > 0.f ? q0 : 0.01f*q0;
        q1 = q1 > 0.f ? q1 : 0.01f*q1;
        float val = q0*w2x + q1*w2y;
        #pragma unroll
        for (int off = 16; off; off >>= 1) val += __shfl_down_sync(0xffffffffu, val, off);
        if (lane == 0) out[row] = val;
    }
}

// ---------------- launch: fork streaming at t=0 (no atomics this time) -------
extern "C" void kernel_launch(void* const* d_in, const int* in_sizes, int n_in,
                              void* d_out, int out_size)
{
    const float* states   = (const float*)d_in[0];
    const float* policies = (const float*)d_in[1];
    const float* actions  = (const float*)d_in[2];
    const float* noise    = (const float*)d_in[3];
    const float* Wk_oa    = (const float*)d_in[4];
    const float* Wq_oa    = (const float*)d_in[5];
    const float* Wv_oa    = (const float*)d_in[6];
    const float* Wk_o     = (const float*)d_in[7];
    const float* Wq_o     = (const float*)d_in[8];
    const float* Wv_o     = (const float*)d_in[9];
    const float* W1       = (const float*)d_in[10];
    const float* W2       = (const float*)d_in[11];
    float* out = (float*)d_out;

    static cudaStream_t s2 = nullptr;
    static cudaEvent_t evA = nullptr, evB = nullptr;
    if (!s2) {
        cudaStreamCreateWithFlags(&s2, cudaStreamNonBlocking);
        cudaEventCreateWithFlags(&evA, cudaEventDisableTiming);
        cudaEventCreateWithFlags(&evB, cudaEventDisableTiming);
    }

    // fork: noise reduction (depends only on noise) runs concurrently
    cudaEventRecord(evA, 0);
    cudaStreamWaitEvent(s2, evA, 0);
    reduce_kernel<<<296, 512, 0, s2>>>((const float4*)noise);
    cudaEventRecord(evB, s2);

    proj_oa_kernel<<<dim3(16,4,4), 256>>>(states, policies, actions,
                                          Wk_oa, Wq_oa, Wv_oa);
    proj_o_kernel<<<dim3(16,3,4), 256>>>(states, Wk_o, Wq_o, Wv_o);
    wtrans_kernel<<<32, 256>>>(W1);
    attac_kernel<<<dim3(16,4), 256>>>(W1, out);

    cudaStreamWaitEvent(0, evB, 0);
    gemv_kernel<<<512, 256>>>(W2, out);
}

// round 15
// speedup vs baseline: 1.9011x; 1.2458x over previous
#include <cuda_runtime.h>

#define BNN 16384   // 16*32*32

// ---------------- scratch (device globals) ----------------------------------
__device__ float g_Koa[512*128];
__device__ float g_Qoa[512*128];
__device__ float g_Voa[512*128];
__device__ float g_Vop[512*128];
__device__ float g_Ko [512*128];
__device__ float g_Qo [512*128];
__device__ float g_AVO[512*128];
__device__ float g_A  [512*64];
__device__ float g_C  [512*64];
__device__ float g_woa[512*32];

__device__ __forceinline__ float dot4(float4 a, float4 b){
    return a.x*b.x + a.y*b.y + a.z*b.z + a.w*b.w;
}

// ---------------- proj (obs-action branch, E=144 compile-time) ---------------
__global__ __launch_bounds__(256) void proj_oa_kernel(
    const float* __restrict__ states, const float* __restrict__ policies,
    const float* __restrict__ actions,
    const float* __restrict__ Wk_oa, const float* __restrict__ Wq_oa,
    const float* __restrict__ Wv_oa)
{
    constexpr int E = 144;
    __shared__ float IN [32*148];
    __shared__ float Wsm[32*148];
    int b = blockIdx.x, m = blockIdx.y, dz = blockIdx.z;
    int tid = threadIdx.x;
    const float* W = (m==0)?Wk_oa:(m==1)?Wq_oa:Wv_oa;
    float* OUT = (m==0)?g_Koa:(m==1)?g_Qoa:(m==2)?g_Voa:g_Vop;
    const float* extra = (m==3) ? policies : actions;

    #pragma unroll
    for (int it = 0; it < 18; it++) {
        int idx = tid + it*256;
        int a = idx / E, e = idx - a*E;
        float v = (e < 128) ? states[(b*32+a)*128 + e]
                            : extra[(b*32+a)*16 + (e-128)];
        IN[a*148 + e] = v;
    }
    #pragma unroll
    for (int it = 0; it < 18; it++) {
        int idx = tid + it*256;
        int r = idx / E, e = idx - r*E;
        Wsm[r*148 + e] = W[(dz*32+r)*E + e];
    }
    __syncthreads();

    int r = tid & 31, g = tid >> 5;
    float acc0=0.f, acc1=0.f, acc2=0.f, acc3=0.f;
    const float4* wr = (const float4*)(Wsm + r*148);
    const float4* x0 = (const float4*)(IN + (g*4+0)*148);
    const float4* x1 = (const float4*)(IN + (g*4+1)*148);
    const float4* x2 = (const float4*)(IN + (g*4+2)*148);
    const float4* x3 = (const float4*)(IN + (g*4+3)*148);
    #pragma unroll
    for (int e4 = 0; e4 < E/4; e4++) {
        float4 w = wr[e4];
        acc0 += dot4(w, x0[e4]);
        acc1 += dot4(w, x1[e4]);
        acc2 += dot4(w, x2[e4]);
        acc3 += dot4(w, x3[e4]);
    }
    int dg = dz*32 + r;
    OUT[(b*32 + g*4+0)*128 + dg] = acc0;
    OUT[(b*32 + g*4+1)*128 + dg] = acc1;
    OUT[(b*32 + g*4+2)*128 + dg] = acc2;
    OUT[(b*32 + g*4+3)*128 + dg] = acc3;
}

// ---------------- proj (obs-only branch, E=128 compile-time) -----------------
__global__ __launch_bounds__(256) void proj_o_kernel(
    const float* __restrict__ states,
    const float* __restrict__ Wk_o, const float* __restrict__ Wq_o,
    const float* __restrict__ Wv_o)
{
    __shared__ float IN [32*132];
    __shared__ float Wsm[32*132];
    int b = blockIdx.x, m = blockIdx.y, dz = blockIdx.z;
    int tid = threadIdx.x;
    const float* W = (m==0)?Wk_o:(m==1)?Wq_o:Wv_o;
    float* OUT = (m==0)?g_Ko:(m==1)?g_Qo:g_AVO;

    const float4* S4 = (const float4*)(states + b*32*128);
    const float4* W4 = (const float4*)(W + dz*32*128);
    #pragma unroll
    for (int it = 0; it < 4; it++) {
        int idx = tid + it*256;               // float4 index
        int a = idx >> 5, e4 = idx & 31;
        *(float4*)(IN  + a*132 + e4*4) = S4[idx];
        *(float4*)(Wsm + a*132 + e4*4) = W4[idx];
    }
    __syncthreads();

    int r = tid & 31, g = tid >> 5;
    float acc0=0.f, acc1=0.f, acc2=0.f, acc3=0.f;
    const float4* wr = (const float4*)(Wsm + r*132);
    const float4* x0 = (const float4*)(IN + (g*4+0)*132);
    const float4* x1 = (const float4*)(IN + (g*4+1)*132);
    const float4* x2 = (const float4*)(IN + (g*4+2)*132);
    const float4* x3 = (const float4*)(IN + (g*4+3)*132);
    #pragma unroll
    for (int e4 = 0; e4 < 32; e4++) {
        float4 w = wr[e4];
        acc0 += dot4(w, x0[e4]);
        acc1 += dot4(w, x1[e4]);
        acc2 += dot4(w, x2[e4]);
        acc3 += dot4(w, x3[e4]);
    }
    int dg = dz*32 + r;
    OUT[(b*32 + g*4+0)*128 + dg] = acc0;
    OUT[(b*32 + g*4+1)*128 + dg] = acc1;
    OUT[(b*32 + g*4+2)*128 + dg] = acc2;
    OUT[(b*32 + g*4+3)*128 + dg] = acc3;
}

// ---------------- kernel 2: fused attention (both branches) + A/C fold -------
__global__ __launch_bounds__(256) void attac_kernel(
    const float* __restrict__ W1, float* __restrict__ out)
{
    __shared__ float sbig[8320];   // att: sQ+sV; ac: W^T (128*65)
    __shared__ float sK[8*128];    // att K rows; later wfo rows
    __shared__ float sS[8*128];    // raw S
    __shared__ float sD[8*128];    // (Vop-Voa)/32
    float* sQ  = sbig;
    float* sV  = sbig + 4224;
    float* sWT = sbig;

    int b = blockIdx.x, q = blockIdx.y, tid = threadIdx.x;
    int kk = tid >> 5, i = tid & 31, k = q*8 + kk;

    for (int p = 0; p < 2; p++) {
        const float* Qp = p ? g_Qo  : g_Qoa;
        const float* Kp = p ? g_Ko  : g_Koa;
        const float* Vp = p ? g_AVO : g_Voa;
        if (p) __syncthreads();
        const float4* Q4 = (const float4*)(Qp + b*32*128);
        const float4* V4 = (const float4*)(Vp + b*32*128);
        for (int idx = tid; idx < 1024; idx += 256) {
            int a = idx >> 5, e4 = idx & 31;
            *(float4*)(sQ + a*132 + e4*4) = Q4[idx];
            ((float4*)sV)[idx] = V4[idx];
        }
        const float4* K4 = (const float4*)(Kp + (b*32 + q*8)*128);
        if (tid < 256) ((float4*)sK)[tid] = K4[tid];
        __syncthreads();

        const float4* qr = (const float4*)(sQ + i*132);
        const float4* kr = (const float4*)(sK + kk*128);
        float acc = 0.f;
        #pragma unroll
        for (int e4 = 0; e4 < 32; e4++) acc += dot4(qr[e4], kr[e4]);
        float v = acc * 0.08838834764831845f;   // 1/sqrt(128)
        float mx = v;
        #pragma unroll
        for (int off = 16; off; off >>= 1) mx = fmaxf(mx, __shfl_xor_sync(0xffffffffu, mx, off));
        float ex = __expf(v - mx);
        float sm = ex;
        #pragma unroll
        for (int off = 16; off; off >>= 1) sm += __shfl_xor_sync(0xffffffffu, sm, off);
        float w = ex / sm;
        out[(p ? 2*BNN : BNN) + (b*32+k)*32 + i] = w;
        if (!p) g_woa[(b*32+k)*32 + i] = w;
        if (p) __syncthreads();

        float4 a4 = make_float4(0.f,0.f,0.f,0.f);
        #pragma unroll
        for (int i2 = 0; i2 < 32; i2++) {
            float wv = __shfl_sync(0xffffffffu, w, i2);
            float4 vv = ((const float4*)sV)[i2*32 + i];
            a4.x += wv*vv.x; a4.y += wv*vv.y; a4.z += wv*vv.z; a4.w += wv*vv.w;
        }
        if (!p) {
            ((float4*)sS)[kk*32 + i] = a4;
        } else {
            float4 sc = make_float4(a4.x*0.03125f, a4.y*0.03125f, a4.z*0.03125f, a4.w*0.03125f);
            ((float4*)sK)[kk*32 + i] = sc;    // wfo
        }
    }
    __syncthreads();

    {
        int base = (b*32 + q*8)*128;
        for (int idx = tid; idx < 1024; idx += 256)
            sD[idx] = (g_Vop[base+idx] - g_Voa[base+idx]) * 0.03125f;
        for (int idx = tid; idx < 8192; idx += 256) {   // W1a^T
            int hh = idx >> 7, e = idx & 127;
            sWT[e*65 + hh] = W1[hh*256 + e];
        }
    }
    __syncthreads();

    int h = tid & 63, grp = tid >> 6;
    const float* wf0 = sK + (grp*2  )*128;
    const float* wf1 = sK + (grp*2+1)*128;
    float accA0 = 0.f, accA1 = 0.f;
    #pragma unroll 4
    for (int e = 0; e < 128; e++) {
        float w = sWT[e*65 + h];
        accA0 += w*wf0[e]; accA1 += w*wf1[e];
    }
    __syncthreads();
    for (int idx = tid; idx < 8192; idx += 256) {       // W1b^T
        int hh = idx >> 7, e = idx & 127;
        sWT[e*65 + hh] = W1[hh*256 + 128 + e];
    }
    __syncthreads();

    const float* s0 = sS + grp*2*128; const float* s1 = s0 + 128;
    const float* d0 = sD + grp*2*128; const float* d1 = d0 + 128;
    float aS0=0.f, aS1=0.f, aD0=0.f, aD1=0.f, aW=0.f;
    #pragma unroll 4
    for (int e = 0; e < 128; e++) {
        float w = sWT[e*65 + h];
        aW  += w;
        aS0 += w*s0[e]; aS1 += w*s1[e];
        aD0 += w*d0[e]; aD1 += w*d1[e];
    }
    int ga = b*32 + q*8 + grp*2;
    g_A[ ga   *64 + h] = accA0 + 0.03125f*aS0 - 0.05f*aW;
    g_A[(ga+1)*64 + h] = accA1 + 0.03125f*aS1 - 0.05f*aW;
    g_C[ ga   *64 + h] = aD0;
    g_C[(ga+1)*64 + h] = aD1;
}

// ---------------- kernel 3: persistent one-wave fused stream+GEMV+epilogue ---
// grid 296 x 512 = 2 CTAs/SM, single wave. Warp processes tiles strided by
// 4736: reduce 16KB noise, GEMV vs smem WT, epilogue from L2-hot A/C/woa.
__global__ __launch_bounds__(512, 2) void fused_kernel(
    const float4* __restrict__ np, const float* __restrict__ W1,
    const float* __restrict__ W2, float* __restrict__ out)
{
    __shared__ float WT [128*66];    // W1b^T [d][h], pad 66 (33.8 KB)
    __shared__ float Msm[16*132];    // per-warp row of i-sums (8.4 KB)

    int tid = threadIdx.x;
    int w = tid >> 5, lane = tid & 31;
    int wgid = blockIdx.x*16 + w;    // 0..4735

    // block-shared W1b^T, coalesced along d
    #pragma unroll
    for (int it = 0; it < 16; it++) {
        int idx = tid + it*512;
        int d = idx & 127, h = idx >> 7;
        WT[d*66 + h] = W1[h*256 + 128 + d];
    }
    __syncthreads();

    float* ms = Msm + w*132;
    const float* wtl = WT + 2*lane;
    float w2x = __ldg(W2 + 2*lane), w2y = __ldg(W2 + 2*lane + 1);

    for (int q = 0; ; q++) {
        int tile = wgid + q*4736;               // b*1024 + k*32 + j
        if (tile >= 16384) break;

        // --- stream-reduce the 32 i-rows of this tile (batch-8 for MLP) ---
        const float4* p = np + ((long)tile << 10) + lane;
        float4 acc = make_float4(0.f,0.f,0.f,0.f);
        #pragma unroll
        for (int bb = 0; bb < 4; bb++) {
            float4 v[8];
            #pragma unroll
            for (int u = 0; u < 8; u++) v[u] = __ldcs(p + ((bb*8 + u) << 5));
            #pragma unroll
            for (int u = 0; u < 8; u++) {
                acc.x += v[u].x; acc.y += v[u].y; acc.z += v[u].z; acc.w += v[u].w;
            }
        }
        *(float4*)(ms + lane*4) = acc;
        __syncwarp();

        // --- GEMV: lane owns h = {2lane, 2lane+1} ---
        float a0 = 0.f, a1 = 0.f;
        #pragma unroll 4
        for (int d = 0; d < 128; d++) {
            float m = ms[d];                          // broadcast
            float2 wv = *(const float2*)(wtl + d*66); // conflict-free
            a0 += m*wv.x; a1 += m*wv.y;
        }

        // --- epilogue ---
        int bk = tile >> 5, b = tile >> 10, j = tile & 31;
        float2 A2 = *(const float2*)(g_A + bk*64 + 2*lane);
        float2 c2 = *(const float2*)(g_C + (b*32 + j)*64 + 2*lane);
        float wo = g_woa[tile];
        float p0 = A2.x + wo*c2.x + 0.003125f*a0;
        float p1 = A2.y + wo*c2.y + 0.003125f*a1;
        p0 = p0 > 0.f ? p0 : 0.01f*p0;
        p1 = p1 > 0.f ? p1 : 0.01f*p1;
        float val = p0*w2x + p1*w2y;
        #pragma unroll
        for (int off = 16; off; off >>= 1) val += __shfl_down_sync(0xffffffffu, val, off);
        if (lane == 0) out[tile] = val;
        __syncwarp();
    }
}

// ---------------- launch (sequential — forks have lost twice) -----------------
extern "C" void kernel_launch(void* const* d_in, const int* in_sizes, int n_in,
                              void* d_out, int out_size)
{
    const float* states   = (const float*)d_in[0];
    const float* policies = (const float*)d_in[1];
    const float* actions  = (const float*)d_in[2];
    const float* noise    = (const float*)d_in[3];
    const float* Wk_oa    = (const float*)d_in[4];
    const float* Wq_oa    = (const float*)d_in[5];
    const float* Wv_oa    = (const float*)d_in[6];
    const float* Wk_o     = (const float*)d_in[7];
    const float* Wq_o     = (const float*)d_in[8];
    const float* Wv_o     = (const float*)d_in[9];
    const float* W1       = (const float*)d_in[10];
    const float* W2       = (const float*)d_in[11];
    float* out = (float*)d_out;

    proj_oa_kernel<<<dim3(16,4,4), 256>>>(states, policies, actions,
                                          Wk_oa, Wq_oa, Wv_oa);
    proj_o_kernel<<<dim3(16,3,4), 256>>>(states, Wk_o, Wq_o, Wv_o);
    attac_kernel<<<dim3(16,4), 256>>>(W1, out);
    fused_kernel<<<296, 512>>>((const float4*)noise, W1, W2, out);
}